// round 16
// baseline (speedup 1.0000x reference)
#include <cuda_runtime.h>
#include <cstdint>

#define B_  1024
#define T_  32
#define D_  64
#define E_  100000
#define L_  50
#define NUM_BAGS (B_ * T_)        // 32768
#define THREADS 128               // 4 warps/CTA
#define BAGS_PER_CTA 4

// Last experiment of the session: the proven per-warp structure (rounds
// 4/9/11/15: 57.5-58.1us, DRAM 74-76% = the random-256B-granule efficiency
// ceiling, traffic at the compulsory unique-row floor) with 128-thread CTAs
// (4 bags) instead of 64-thread (2 bags): 8192 CTAs instead of 16384, halving
// wave-transition churn. Warps/SM (16), smem/SM (205KB), regs, and the
// per-warp pipeline are unchanged. Prior two attempts hit broker-level
// container failures (uncorrelated with kernel content per round-10/11).
//  - one warp per bag; 25 cp.async.cg pair-loads (512B each: lanes 0-15
//    even row, 16-31 odd, 16B/lane) in 5 commit groups
//  - progressive wait_group + reduce (up to 20 loads in flight)
//  - indices staged via one LDG.64 across 25 lanes
//  - table-grouped bag remap (new_bag = t*1024 + b) for L2 repeat-row reuse

template<int N>
__device__ __forceinline__ void cp_wait_group() {
    asm volatile("cp.async.wait_group %0;\n" :: "n"(N) : "memory");
}

__global__ void __launch_bounds__(THREADS, 4)
embedding_bags_kernel(const float* __restrict__ weights,   // (E, T, D)
                      const int*   __restrict__ features,  // (B*T*L)
                      float*       __restrict__ out)       // (B*T, D)
{
    __shared__ __align__(16) float4 srows[BAGS_PER_CTA * L_ * 16]; // 51200B
    __shared__ __align__(8)  int2   sidx2[BAGS_PER_CTA * 32];      // 1024B

    const int warp = threadIdx.x >> 5;
    const int lane = threadIdx.x & 31;
    const int half = lane >> 4;            // 0: even row of pair, 1: odd
    const int sub  = lane & 15;            // 16B chunk within 256B row

    // Table-grouped remap: new_bag = t*1024 + b  ->  orig bag = b*32 + t
    const int new_bag  = blockIdx.x * BAGS_PER_CTA + warp;
    const int t        = new_bag >> 10;
    const int b        = new_bag & 1023;
    const int bag_orig = (b << 5) | t;

    // Stage 50 indices: 25 lanes each load one int2 (8B aligned: 200B/bag).
    const int2* __restrict__ idxp2 =
        reinterpret_cast<const int2*>(features + (size_t)bag_orig * L_);
    int2* __restrict__ myidx2 = sidx2 + warp * 32;
    if (lane < 25) myidx2[lane] = __ldg(idxp2 + lane);
    __syncwarp();
    const int* __restrict__ myidx = reinterpret_cast<const int*>(myidx2);

    // row (idx, t) as float4: idx*(T*D/4) + t*(D/4) + sub
    const float4* __restrict__ gbase =
        reinterpret_cast<const float4*>(weights) + (size_t)t * (D_ / 4) + sub;

    float4* __restrict__ sbuf = srows + warp * (L_ * 16);
    const uint32_t sbase = (uint32_t)__cvta_generic_to_shared(sbuf);

    // Issue 25 independent pair-loads in 5 commit groups
    #pragma unroll
    for (int g = 0; g < 5; ++g) {
        #pragma unroll
        for (int p = 0; p < 5; ++p) {
            const int r   = 2 * (g * 5 + p) + half;   // row slot 0..49
            const int idx = myidx[r];
            const float4* src = gbase + (size_t)idx * (T_ * D_ / 4);
            const uint32_t dst = sbase + (uint32_t)(r * 256 + sub * 16);
            asm volatile("cp.async.cg.shared.global [%0], [%1], 16;\n"
                         :: "r"(dst), "l"(src) : "memory");
        }
        asm volatile("cp.async.commit_group;\n" ::: "memory");
    }

    float4 acc = make_float4(0.0f, 0.0f, 0.0f, 0.0f);

    // Progressive reduce; each lane reads only bytes it wrote itself.
#define REDUCE_GROUP(G)                                              \
    cp_wait_group<4 - (G)>();                                        \
    _Pragma("unroll")                                                \
    for (int p = 0; p < 5; ++p) {                                    \
        const int r = 2 * ((G) * 5 + p) + half;                      \
        float4 v = sbuf[r * 16 + sub];                               \
        acc.x += v.x; acc.y += v.y; acc.z += v.z; acc.w += v.w;      \
    }

    REDUCE_GROUP(0)
    REDUCE_GROUP(1)
    REDUCE_GROUP(2)
    REDUCE_GROUP(3)
    REDUCE_GROUP(4)
#undef REDUCE_GROUP

    // Merge even-row half and odd-row half
    acc.x += __shfl_xor_sync(0xffffffffu, acc.x, 16);
    acc.y += __shfl_xor_sync(0xffffffffu, acc.y, 16);
    acc.z += __shfl_xor_sync(0xffffffffu, acc.z, 16);
    acc.w += __shfl_xor_sync(0xffffffffu, acc.w, 16);

    if (half == 0) {
        reinterpret_cast<float4*>(out)[(size_t)bag_orig * (D_ / 4) + sub] = acc;
    }
}

extern "C" void kernel_launch(void* const* d_in, const int* in_sizes, int n_in,
                              void* d_out, int out_size)
{
    const float* weights  = (const float*)d_in[0];
    const int*   features = (const int*)  d_in[1];
    float* out = (float*)d_out;

    const int blocks = NUM_BAGS / BAGS_PER_CTA;   // 8192
    embedding_bags_kernel<<<blocks, THREADS>>>(weights, features, out);
}